// round 16
// baseline (speedup 1.0000x reference)
#include <cuda_runtime.h>
#include <cstdint>

#define SLOPE 0.01f
#define EPSBN 1e-5f
#define NPOS  65536
#define S72   72      // activation tile stride: ==8 mod 32 -> mma B loads conflict-free
#define TPAD  132     // xr row stride

// ---------------- device scratch ----------------
__device__ float g_w1t[16384];        // cl1 [k][o] BN-folded (scalar)
__device__ float g_w3t[16384];        // cl3 logits rows (scalar)
__device__ uint32_t g_wA1[16384];     // reg1 tf32-hi A-fragments (NS1)
__device__ uint32_t g_wA2[3][16384];  // cl2 tf32 3-split A-fragments (NS3)
__device__ float g_b1[128], g_br[128], g_b2[128], g_b3[128], g_wm[128];
__device__ float g_bm;
__device__ float4 g_moe4[131072];

__device__ __forceinline__ float lrelu(float v) { return v >= 0.0f ? v : SLOPE * v; }

__device__ __forceinline__ unsigned long long pk2(float x) {
    unsigned long long r;
    asm("mov.b64 %0, {%1, %1};" : "=l"(r) : "f"(x));
    return r;
}
__device__ __forceinline__ void fma2(unsigned long long& d,
                                     unsigned long long a, unsigned long long b) {
    asm("fma.rn.f32x2 %0, %1, %2, %0;" : "+l"(d) : "l"(a), "l"(b));
}
__device__ __forceinline__ float2 up2(unsigned long long v) {
    float2 r;
    asm("mov.b64 {%0, %1}, %2;" : "=f"(r.x), "=f"(r.y) : "l"(v));
    return r;
}
__device__ __forceinline__ uint32_t tf32_of(float x) {
    uint32_t r;
    asm("cvt.rna.tf32.f32 %0, %1;" : "=r"(r) : "f"(x));
    return r;
}
__device__ __forceinline__ void mma8(float* c, const uint4 a, uint32_t b0, uint32_t b1) {
    asm volatile(
        "mma.sync.aligned.m16n8k8.row.col.f32.tf32.tf32.f32 "
        "{%0,%1,%2,%3}, {%4,%5,%6,%7}, {%8,%9}, {%0,%1,%2,%3};"
        : "+f"(c[0]), "+f"(c[1]), "+f"(c[2]), "+f"(c[3])
        : "r"(a.x), "r"(a.y), "r"(a.z), "r"(a.w), "r"(b0), "r"(b1));
}

// ---------------- prep ----------------
__global__ void prep_kernel(const float* __restrict__ cl1_w, const float* __restrict__ cl1_b,
                            const float* __restrict__ g1,    const float* __restrict__ be1,
                            const float* __restrict__ m1,    const float* __restrict__ v1,
                            const float* __restrict__ cl2_w, const float* __restrict__ cl2_b,
                            const float* __restrict__ cl3_w, const float* __restrict__ cl3_b,
                            const float* __restrict__ reg1_w,const float* __restrict__ reg1_b,
                            const float* __restrict__ gr,    const float* __restrict__ ber,
                            const float* __restrict__ mr,    const float* __restrict__ vr,
                            const float* __restrict__ cm2_w)
{
    int tid = blockIdx.x * blockDim.x + threadIdx.x;   // 0..131071

    {   // MoE repack
        int e  = tid >> 10;
        int cg = (tid >> 5) & 31;
        int j  = tid & 31;
        const float* src = cm2_w + e * 4096 + (cg * 4) * 32 + j;
        g_moe4[tid] = make_float4(src[0], src[32], src[64], src[96]);
    }

    if (tid < 65536) {
        int l = tid >> 14, o = (tid >> 7) & 127, k = tid & 127;
        // m16n8k8 A-fragment slot (shared by NS1/NS3 bakes)
        int mtg = o >> 4;
        int gg  = o & 7, hh = (o >> 3) & 1;
        int kc  = k >> 3, tig = k & 3, kh = (k >> 2) & 1;
        int lane = gg * 4 + tig, reg = hh + 2 * kh;
        int fi = (kc * 8 + mtg) * 128 + lane * 4 + reg;

        if (l == 0) {
            g_w1t[k * 128 + o] = cl1_w[o * 128 + k] * (g1[o] * rsqrtf(v1[o] + EPSBN));
        } else if (l == 1) {
            float wv = reg1_w[o * 128 + k] * (gr[o] * rsqrtf(vr[o] + EPSBN));
            g_wA1[fi] = tf32_of(wv);
        } else if (l == 2) {
            float wv = cl2_w[o * 128 + k];
            uint32_t sh = tf32_of(wv);
            float r1v = wv - __uint_as_float(sh);
            uint32_t smid = tf32_of(r1v);
            uint32_t sl = tf32_of(r1v - __uint_as_float(smid));
            g_wA2[0][fi] = sh;
            g_wA2[1][fi] = smid;
            g_wA2[2][fi] = sl;
        } else {
            g_w3t[k * 128 + o] = cl3_w[o * 128 + k];
        }
    }
    if (tid < 128) {
        float s = g1[tid] * rsqrtf(v1[tid] + EPSBN);
        g_b1[tid] = cl1_b[tid] * s + be1[tid] - m1[tid] * s;
        float s2 = gr[tid] * rsqrtf(vr[tid] + EPSBN);
        g_br[tid] = reg1_b[tid] * s2 + ber[tid] - mr[tid] * s2;
        g_b2[tid] = cl2_b[tid];
        g_b3[tid] = cl3_b[tid];
        g_wm[tid] = cl3_w[128 * 128 + tid];
        if (tid == 0) g_bm = cl3_b[128];
    }
}

// ---------------- scalar 128x128x64 GEMM (FFMA2), 4-row weight chunks ----------------
// Warp w: channels 32w..32w+31; thread tile 8ch x 8pos. sWb: 4 x 128 floats.
template<int IS>
__device__ __forceinline__ void gemm_tile_s(const float* __restrict__ wT,
                                            const float* sIn, float* sWb,
                                            float f[8][8])
{
    const int t    = threadIdx.x;
    const int warp = t >> 5, lane = t & 31;
    const int ty   = t >> 3, tx = t & 7;
    const int tyl  = ty & 3;
    const float4* wg  = (const float4*)wT;
    float*  sW  = sWb + warp * 128;         // [4 k][32 ch]
    float4* ws4 = (float4*)sW;

    unsigned long long acc[4][8];
#pragma unroll
    for (int i = 0; i < 4; i++)
#pragma unroll
        for (int j = 0; j < 8; j++) acc[i][j] = 0ull;

    // prefetch chunk 0: [4k][32ch] = 32 float4, 1/lane
    float4 p = wg[(lane >> 3) * 32 + warp * 8 + (lane & 7)];

#pragma unroll 1
    for (int c4 = 0; c4 < 32; c4++) {
        ws4[lane] = p;          // lane = (lane>>3)*8 + (lane&7): [k][c4] layout
        __syncwarp();
        if (c4 < 31)
            p = wg[((c4 + 1) * 4 + (lane >> 3)) * 32 + warp * 8 + (lane & 7)];
        const float* inb = sIn + c4 * 4 * IS;
#pragma unroll
        for (int k = 0; k < 4; k++) {
            ulonglong2 a01 = *(const ulonglong2*)(sW + k * 32 + tyl * 8);
            ulonglong2 a23 = *(const ulonglong2*)(sW + k * 32 + tyl * 8 + 4);
            float4 xlo = *(const float4*)(inb + k * IS + tx * 4);
            float4 xhi = *(const float4*)(inb + k * IS + 32 + tx * 4);
            unsigned long long b[8];
            b[0] = pk2(xlo.x); b[1] = pk2(xlo.y); b[2] = pk2(xlo.z); b[3] = pk2(xlo.w);
            b[4] = pk2(xhi.x); b[5] = pk2(xhi.y); b[6] = pk2(xhi.z); b[7] = pk2(xhi.w);
#pragma unroll
            for (int j = 0; j < 8; j++) {
                fma2(acc[0][j], a01.x, b[j]);
                fma2(acc[1][j], a01.y, b[j]);
                fma2(acc[2][j], a23.x, b[j]);
                fma2(acc[3][j], a23.y, b[j]);
            }
        }
        __syncwarp();
    }

#pragma unroll
    for (int ip = 0; ip < 4; ip++)
#pragma unroll
        for (int j = 0; j < 8; j++) {
            float2 u = up2(acc[ip][j]);
            f[2 * ip][j]     = u.x;
            f[2 * ip + 1][j] = u.y;
        }
}

__device__ __forceinline__ void store_act_s(float* dst, const float* bias,
                                            float f[8][8], int ty, int tx)
{
#pragma unroll
    for (int i = 0; i < 8; i++) {
        float bi = bias[ty * 8 + i];
#pragma unroll
        for (int j = 0; j < 8; j++) f[i][j] = lrelu(f[i][j] + bi);
        *(float4*)(dst + (ty * 8 + i) * S72 + tx * 4) =
            make_float4(f[i][0], f[i][1], f[i][2], f[i][3]);
        *(float4*)(dst + (ty * 8 + i) * S72 + 32 + tx * 4) =
            make_float4(f[i][4], f[i][5], f[i][6], f[i][7]);
    }
}

// ---------------- R1 via NS1 tf32 mma ----------------
__device__ __forceinline__ void gemm_r1(const float* __restrict__ sIn,
                                        float acc[2][8][4], int w, int lane)
{
    const uint4* A0 = (const uint4*)g_wA1;
    const int g = lane >> 2, tig = lane & 3;
#pragma unroll
    for (int mt = 0; mt < 2; mt++)
#pragma unroll
        for (int n = 0; n < 8; n++)
#pragma unroll
            for (int c = 0; c < 4; c++) acc[mt][n][c] = 0.0f;

    uint4 Ab[2][2];
    {
        int fo = (2 * w) * 32 + lane;
        Ab[0][0] = __ldg(A0 + fo);
        Ab[0][1] = __ldg(A0 + fo + 32);
    }
#pragma unroll 1
    for (int kc = 0; kc < 16; kc++) {
        int cur = kc & 1;
        if (kc < 15) {
            int fo = ((kc + 1) * 8 + 2 * w) * 32 + lane;
            Ab[cur ^ 1][0] = __ldg(A0 + fo);
            Ab[cur ^ 1][1] = __ldg(A0 + fo + 32);
        }
        const float* bp = sIn + (kc * 8 + tig) * S72 + g;
#pragma unroll
        for (int n = 0; n < 8; n++) {
            float x0 = bp[8 * n], x1 = bp[4 * S72 + 8 * n];
            uint32_t h0 = tf32_of(x0), h1 = tf32_of(x1);
            mma8(acc[0][n], Ab[cur][0], h0, h1);
            mma8(acc[1][n], Ab[cur][1], h0, h1);
        }
    }
}

// ---------------- L2 via NS3 tf32 mma (6-product, error ~2^-33) ----------------
__device__ __forceinline__ void gemm_l2(const float* __restrict__ sIn,
                                        float acc[2][8][4], int w, int lane)
{
    const uint4* A0 = (const uint4*)g_wA2[0];
    const uint4* A1 = (const uint4*)g_wA2[1];
    const uint4* A2 = (const uint4*)g_wA2[2];
    const int g = lane >> 2, tig = lane & 3;
#pragma unroll
    for (int mt = 0; mt < 2; mt++)
#pragma unroll
        for (int n = 0; n < 8; n++)
#pragma unroll
            for (int c = 0; c < 4; c++) acc[mt][n][c] = 0.0f;

    uint4 Ab[2][2][3];
    {
        int fo = (2 * w) * 32 + lane;
#pragma unroll
        for (int mt = 0; mt < 2; mt++) {
            Ab[0][mt][0] = __ldg(A0 + fo + mt * 32);
            Ab[0][mt][1] = __ldg(A1 + fo + mt * 32);
            Ab[0][mt][2] = __ldg(A2 + fo + mt * 32);
        }
    }
#pragma unroll 1
    for (int kc = 0; kc < 16; kc++) {
        int cur = kc & 1;
        if (kc < 15) {
            int fo = ((kc + 1) * 8 + 2 * w) * 32 + lane;
#pragma unroll
            for (int mt = 0; mt < 2; mt++) {
                Ab[cur ^ 1][mt][0] = __ldg(A0 + fo + mt * 32);
                Ab[cur ^ 1][mt][1] = __ldg(A1 + fo + mt * 32);
                Ab[cur ^ 1][mt][2] = __ldg(A2 + fo + mt * 32);
            }
        }
        const float* bp = sIn + (kc * 8 + tig) * S72 + g;
#pragma unroll
        for (int n = 0; n < 8; n++) {
            float x0 = bp[8 * n], x1 = bp[4 * S72 + 8 * n];
            uint32_t h0 = tf32_of(x0), h1 = tf32_of(x1);
            float r0 = x0 - __uint_as_float(h0), r1 = x1 - __uint_as_float(h1);
            uint32_t m0 = tf32_of(r0), m1 = tf32_of(r1);
            uint32_t l0 = tf32_of(r0 - __uint_as_float(m0));
            uint32_t l1 = tf32_of(r1 - __uint_as_float(m1));
#pragma unroll
            for (int mt = 0; mt < 2; mt++) {
                mma8(acc[mt][n], Ab[cur][mt][0], h0, h1);   // hh
                mma8(acc[mt][n], Ab[cur][mt][0], m0, m1);   // hm
                mma8(acc[mt][n], Ab[cur][mt][1], h0, h1);   // mh
                mma8(acc[mt][n], Ab[cur][mt][0], l0, l1);   // hl
                mma8(acc[mt][n], Ab[cur][mt][2], h0, h1);   // lh
                mma8(acc[mt][n], Ab[cur][mt][1], m0, m1);   // mm
            }
        }
    }
}

// ---------------- fused main kernel (128 threads, 3 CTAs/SM) ----------------
__global__ void __launch_bounds__(128, 3)
fused_kernel(const float* __restrict__ x_in,
             const float* __restrict__ cm2_b,
             const float* __restrict__ cm3_w, const float* __restrict__ cm3_b,
             float* __restrict__ out)
{
    extern __shared__ float sm[];
    float* sA   = sm;                      // x tile [128][S72] (9216 floats)
    float* sXR  = sm;                      // xr [64][TPAD] (8448, aliases sA)
    int*   sInd = (int*)(sm + 8448);       // 64 (sA tail, free after R1)
    float* sB   = sm + 9216;               // y tile [128][S72] (9216)
    float* sW   = sB + 9216;               // 4 x 128 staging (512)
    float* sRv  = sW;                      // alias after L3: 4*64 vals
    int*   sRi  = (int*)(sW + 256);        // 4*64 idx

    const int t = threadIdx.x, w = t >> 5, lane = t & 31;
    const int ty = t >> 3, tx = t & 7;
    const int g = lane >> 2, tig = lane & 3;
    const int bb = blockIdx.x >> 7;
    const int w0 = (blockIdx.x & 127) * 64;
    const float* xb = x_in + (size_t)bb * 128 * 8192 + w0;

    // stage x tile [ch][S72]
#pragma unroll
    for (int j = 0; j < 16; j++) {
        int idx = t + j * 128;
        int c = idx >> 4, p4 = idx & 15;
        float4 v = *(const float4*)(xb + c * 8192 + p4 * 4);
        *(float4*)(sA + c * S72 + p4 * 4) = v;
    }
    __syncthreads();   // (1) x visible

    float f[8][8];

    // ---- L1 scalar (exact): y1 = lrelu(bn(cl1 @ x)) : sA -> sB ----
    gemm_tile_s<S72>(g_w1t, sA, sW, f);
    store_act_s(sB, g_b1, f, ty, tx);

    // ---- R1 mma NS1: xr = lrelu(bn(reg1 @ x)) : sA -> sXR (transposed) ----
    {
        float acc[2][8][4];
        gemm_r1(sA, acc, w, lane);
        __syncthreads();   // (2) all sA reads done; y1 stores visible
#pragma unroll
        for (int mt = 0; mt < 2; mt++)
#pragma unroll
            for (int h = 0; h < 2; h++) {
                int ch = 32 * w + 16 * mt + g + 8 * h;
                float bi = g_br[ch];
#pragma unroll
                for (int n = 0; n < 8; n++) {
                    int pos = 8 * n + 2 * tig;
                    sXR[pos * TPAD + ch]       = lrelu(acc[mt][n][2 * h]     + bi);
                    sXR[(pos + 1) * TPAD + ch] = lrelu(acc[mt][n][2 * h + 1] + bi);
                }
            }
    }

    // ---- L2 mma NS3 (exact-grade): y2 = lrelu(cl2 @ y1) : sB -> sB ----
    {
        float acc[2][8][4];
        gemm_l2(sB, acc, w, lane);
        __syncthreads();   // (3) all warps done reading y1
#pragma unroll
        for (int mt = 0; mt < 2; mt++)
#pragma unroll
            for (int h = 0; h < 2; h++) {
                int ch = 32 * w + 16 * mt + g + 8 * h;
                float bi = g_b2[ch];
#pragma unroll
                for (int n = 0; n < 8; n++) {
                    float v0 = lrelu(acc[mt][n][2 * h]     + bi);
                    float v1 = lrelu(acc[mt][n][2 * h + 1] + bi);
                    *(float2*)(sB + ch * S72 + 8 * n + 2 * tig) = make_float2(v0, v1);
                }
            }
        __syncthreads();   // (4) y2 visible
    }

    // ---- L3 scalar (exact): logits : sB -> regs ----
    gemm_tile_s<S72>(g_w3t, sB, sW, f);
    __syncthreads();   // (5) sW staging free -> argmax alias OK

    // per-thread argmax over 8 ch, shfl-reduce over ty-groups in warp
    {
        float bv[8];
        int   bi[8];
#pragma unroll
        for (int j = 0; j < 8; j++) {
            float best = f[0][j] + g_b3[ty * 8];
            int bidx = ty * 8;
#pragma unroll
            for (int i = 1; i < 8; i++) {
                float v = f[i][j] + g_b3[ty * 8 + i];
                if (v > best) { best = v; bidx = ty * 8 + i; }
            }
            bv[j] = best; bi[j] = bidx;
        }
#pragma unroll
        for (int off = 8; off <= 16; off <<= 1)
#pragma unroll
            for (int j = 0; j < 8; j++) {
                float ov = __shfl_xor_sync(0xffffffffu, bv[j], off);
                int   oi = __shfl_xor_sync(0xffffffffu, bi[j], off);
                if (ov > bv[j] || (ov == bv[j] && oi < bi[j])) { bv[j] = ov; bi[j] = oi; }
            }
        if (lane < 8) {
#pragma unroll
            for (int j = 0; j < 8; j++) {
                int pos = (j < 4) ? (tx * 4 + j) : (32 + tx * 4 + j - 4);
                sRv[w * 64 + pos] = bv[j];
                sRi[w * 64 + pos] = bi[j];
            }
        }
    }
    __syncthreads();   // (6) argmax partials visible

    if (t < 64) {
        float bvv = sRv[t];
        int bii = sRi[t];
#pragma unroll
        for (int r = 1; r < 4; r++) {
            float v = sRv[r * 64 + t];
            if (v > bvv) { bvv = v; bii = sRi[r * 64 + t]; }
        }
        sInd[t] = bii;
    } else {
        int p = t - 64;
        float m0 = g_bm, m1 = 0.0f, m2 = 0.0f, m3 = 0.0f;
#pragma unroll 8
        for (int k = 0; k < 128; k += 4) {
            m0 = fmaf(sB[(k + 0) * S72 + p], g_wm[k + 0], m0);
            m1 = fmaf(sB[(k + 1) * S72 + p], g_wm[k + 1], m1);
            m2 = fmaf(sB[(k + 2) * S72 + p], g_wm[k + 2], m2);
            m3 = fmaf(sB[(k + 3) * S72 + p], g_wm[k + 3], m3);
        }
        out[NPOS + bb * 8192 + w0 + p] = lrelu((m0 + m1) + (m2 + m3));
    }
    __syncthreads();   // (7) sInd visible

    // ---- MoE regression: 4 warps x 16 positions ----
#pragma unroll 1
    for (int pi = 0; pi < 16; pi++) {
        int pos = w * 16 + pi;
        int ind = sInd[pos];
        const float4* W4 = g_moe4 + ind * 1024 + lane;
        const float4* X4 = (const float4*)(sXR + pos * TPAD);
        float h[4] = {0.0f, 0.0f, 0.0f, 0.0f};
#pragma unroll
        for (int blk = 0; blk < 4; blk++) {
            float4 wv[8];
#pragma unroll
            for (int u = 0; u < 8; u++)
                wv[u] = __ldg(W4 + (blk * 8 + u) * 32);
            float4 x[8];
#pragma unroll
            for (int u = 0; u < 8; u++)
                x[u] = X4[blk * 8 + u];
#pragma unroll
            for (int u = 0; u < 8; u++) {
                float s = h[u & 3];
                s = fmaf(x[u].x, wv[u].x, s);
                s = fmaf(x[u].y, wv[u].y, s);
                s = fmaf(x[u].z, wv[u].z, s);
                s = fmaf(x[u].w, wv[u].w, s);
                h[u & 3] = s;
            }
        }
        float hs = lrelu((h[0] + h[1]) + (h[2] + h[3]) + __ldg(cm2_b + ind * 32 + lane));
        float r = hs * __ldg(cm3_w + ind * 32 + lane);
#pragma unroll
        for (int off = 16; off; off >>= 1)
            r += __shfl_down_sync(0xffffffffu, r, off);
        if (lane == 0)
            out[bb * 8192 + w0 + pos] =
                ((float)ind + r + __ldg(cm3_b + ind)) * (1.0f / 128.0f);
    }
}

// ---------------- launch ----------------
extern "C" void kernel_launch(void* const* d_in, const int* in_sizes, int n_in,
                              void* d_out, int out_size)
{
    const float* x_in  = (const float*)d_in[0];
    const float* cl1_w = (const float*)d_in[1];
    const float* cl1_b = (const float*)d_in[2];
    const float* bn1_g = (const float*)d_in[3];
    const float* bn1_b = (const float*)d_in[4];
    const float* bn1_m = (const float*)d_in[5];
    const float* bn1_v = (const float*)d_in[6];
    const float* cl2_w = (const float*)d_in[7];
    const float* cl2_b = (const float*)d_in[8];
    const float* cl3_w = (const float*)d_in[9];
    const float* cl3_b = (const float*)d_in[10];
    const float* reg1_w = (const float*)d_in[11];
    const float* reg1_b = (const float*)d_in[12];
    const float* bnr_g = (const float*)d_in[13];
    const float* bnr_b = (const float*)d_in[14];
    const float* bnr_m = (const float*)d_in[15];
    const float* bnr_v = (const float*)d_in[16];
    const float* cm2_w = (const float*)d_in[17];
    const float* cm2_b = (const float*)d_in[18];
    const float* cm3_w = (const float*)d_in[19];
    const float* cm3_b = (const float*)d_in[20];
    float* out = (float*)d_out;

    const int SMEM_BYTES = (9216 + 9216 + 512) * 4;   // 75776 B -> 3 CTAs/SM

    cudaFuncSetAttribute(fused_kernel, cudaFuncAttributeMaxDynamicSharedMemorySize,
                         SMEM_BYTES);

    prep_kernel<<<512, 256>>>(cl1_w, cl1_b, bn1_g, bn1_b, bn1_m, bn1_v,
                              cl2_w, cl2_b, cl3_w, cl3_b,
                              reg1_w, reg1_b, bnr_g, bnr_b, bnr_m, bnr_v,
                              cm2_w);

    fused_kernel<<<1024, 128, SMEM_BYTES>>>(x_in, cm2_b, cm3_w, cm3_b, out);
}

// round 17
// speedup vs baseline: 1.0387x; 1.0387x over previous
#include <cuda_runtime.h>
#include <cstdint>

#define SLOPE 0.01f
#define EPSBN 1e-5f
#define NPOS  65536
#define S72   72      // activation tile stride: ==8 mod 32 -> mma B loads conflict-free
#define TPAD  132     // xr row stride

// ---------------- device scratch ----------------
__device__ float g_w1t[16384];        // cl1 [k][o] BN-folded (scalar)
__device__ float g_w2t[16384];        // cl2 (scalar)
__device__ float g_w3t[16384];        // cl3 logits rows (scalar)
__device__ uint32_t g_wA1[16384];     // reg1 tf32-hi A-fragments (NS1)
__device__ float g_b1[128], g_br[128], g_b2[128], g_b3[128], g_wm[128];
__device__ float g_bm;
__device__ float4 g_moe4[131072];

__device__ __forceinline__ float lrelu(float v) { return v >= 0.0f ? v : SLOPE * v; }

__device__ __forceinline__ unsigned long long pk2(float x) {
    unsigned long long r;
    asm("mov.b64 %0, {%1, %1};" : "=l"(r) : "f"(x));
    return r;
}
__device__ __forceinline__ void fma2(unsigned long long& d,
                                     unsigned long long a, unsigned long long b) {
    asm("fma.rn.f32x2 %0, %1, %2, %0;" : "+l"(d) : "l"(a), "l"(b));
}
__device__ __forceinline__ float2 up2(unsigned long long v) {
    float2 r;
    asm("mov.b64 {%0, %1}, %2;" : "=f"(r.x), "=f"(r.y) : "l"(v));
    return r;
}
__device__ __forceinline__ uint32_t tf32_of(float x) {
    uint32_t r;
    asm("cvt.rna.tf32.f32 %0, %1;" : "=r"(r) : "f"(x));
    return r;
}
__device__ __forceinline__ void mma8(float* c, const uint4 a, uint32_t b0, uint32_t b1) {
    asm volatile(
        "mma.sync.aligned.m16n8k8.row.col.f32.tf32.tf32.f32 "
        "{%0,%1,%2,%3}, {%4,%5,%6,%7}, {%8,%9}, {%0,%1,%2,%3};"
        : "+f"(c[0]), "+f"(c[1]), "+f"(c[2]), "+f"(c[3])
        : "r"(a.x), "r"(a.y), "r"(a.z), "r"(a.w), "r"(b0), "r"(b1));
}

// ---------------- prep (identical to R15) ----------------
__global__ void prep_kernel(const float* __restrict__ cl1_w, const float* __restrict__ cl1_b,
                            const float* __restrict__ g1,    const float* __restrict__ be1,
                            const float* __restrict__ m1,    const float* __restrict__ v1,
                            const float* __restrict__ cl2_w, const float* __restrict__ cl2_b,
                            const float* __restrict__ cl3_w, const float* __restrict__ cl3_b,
                            const float* __restrict__ reg1_w,const float* __restrict__ reg1_b,
                            const float* __restrict__ gr,    const float* __restrict__ ber,
                            const float* __restrict__ mr,    const float* __restrict__ vr,
                            const float* __restrict__ cm2_w)
{
    int tid = blockIdx.x * blockDim.x + threadIdx.x;   // 0..131071

    {   // MoE repack
        int e  = tid >> 10;
        int cg = (tid >> 5) & 31;
        int j  = tid & 31;
        const float* src = cm2_w + e * 4096 + (cg * 4) * 32 + j;
        g_moe4[tid] = make_float4(src[0], src[32], src[64], src[96]);
    }

    if (tid < 65536) {
        int l = tid >> 14, o = (tid >> 7) & 127, k = tid & 127;
        if (l == 0) {
            g_w1t[k * 128 + o] = cl1_w[o * 128 + k] * (g1[o] * rsqrtf(v1[o] + EPSBN));
        } else if (l == 1) {
            float wv = reg1_w[o * 128 + k] * (gr[o] * rsqrtf(vr[o] + EPSBN));
            int mtg = o >> 4;
            int gg  = o & 7, hh = (o >> 3) & 1;
            int kc  = k >> 3, tig = k & 3, kh = (k >> 2) & 1;
            int lane = gg * 4 + tig, reg = hh + 2 * kh;
            g_wA1[(kc * 8 + mtg) * 128 + lane * 4 + reg] = tf32_of(wv);
        } else if (l == 2) {
            g_w2t[k * 128 + o] = cl2_w[o * 128 + k];
        } else {
            g_w3t[k * 128 + o] = cl3_w[o * 128 + k];
        }
    }
    if (tid < 128) {
        float s = g1[tid] * rsqrtf(v1[tid] + EPSBN);
        g_b1[tid] = cl1_b[tid] * s + be1[tid] - m1[tid] * s;
        float s2 = gr[tid] * rsqrtf(vr[tid] + EPSBN);
        g_br[tid] = reg1_b[tid] * s2 + ber[tid] - mr[tid] * s2;
        g_b2[tid] = cl2_b[tid];
        g_b3[tid] = cl3_b[tid];
        g_wm[tid] = cl3_w[128 * 128 + tid];
        if (tid == 0) g_bm = cl3_b[128];
    }
}

// ---------------- scalar 16ch-per-warp GEMM (FFMA2), 8-row weight chunks ----------------
// 8 warps: warp w owns channels 16w..16w+15. Thread tile 4ch x 8pos.
// sWb: 8 x 128 floats warp-private staging ([8 k][16 ch] per chunk, 16 chunks).
// k order ascending (bit-identical accumulation vs R15).
__device__ __forceinline__ void gemm16(const float* __restrict__ wT,
                                       const float* sIn, float* sWb,
                                       float f[4][8])
{
    const int t    = threadIdx.x;
    const int warp = t >> 5, lane = t & 31;
    const int ty   = lane >> 3, tx = lane & 7;
    const float4* wg  = (const float4*)wT;
    float*  sW  = sWb + warp * 128;
    float4* ws4 = (float4*)sW;

    unsigned long long acc[2][8];
#pragma unroll
    for (int i = 0; i < 2; i++)
#pragma unroll
        for (int j = 0; j < 8; j++) acc[i][j] = 0ull;

    // prefetch chunk 0: [8k][16ch] = 32 float4, 1/lane
    float4 p = wg[(lane >> 2) * 32 + warp * 4 + (lane & 3)];

#pragma unroll 1
    for (int c8 = 0; c8 < 16; c8++) {
        ws4[lane] = p;                 // [k=lane>>2][c4=lane&3]
        __syncwarp();
        if (c8 < 15)
            p = wg[((c8 + 1) * 8 + (lane >> 2)) * 32 + warp * 4 + (lane & 3)];
        const float* inb = sIn + c8 * 8 * S72;
#pragma unroll
        for (int k = 0; k < 8; k++) {
            ulonglong2 a01 = *(const ulonglong2*)(sW + k * 16 + ty * 4);
            float4 xlo = *(const float4*)(inb + k * S72 + tx * 4);
            float4 xhi = *(const float4*)(inb + k * S72 + 32 + tx * 4);
            unsigned long long b[8];
            b[0] = pk2(xlo.x); b[1] = pk2(xlo.y); b[2] = pk2(xlo.z); b[3] = pk2(xlo.w);
            b[4] = pk2(xhi.x); b[5] = pk2(xhi.y); b[6] = pk2(xhi.z); b[7] = pk2(xhi.w);
#pragma unroll
            for (int j = 0; j < 8; j++) {
                fma2(acc[0][j], a01.x, b[j]);
                fma2(acc[1][j], a01.y, b[j]);
            }
        }
        __syncwarp();
    }

#pragma unroll
    for (int ip = 0; ip < 2; ip++)
#pragma unroll
        for (int j = 0; j < 8; j++) {
            float2 u = up2(acc[ip][j]);
            f[2 * ip][j]     = u.x;
            f[2 * ip + 1][j] = u.y;
        }
}

// epilogue: lrelu(f + bias) -> dst[ch][S72], ch = 16*warp + ty*4 + i
__device__ __forceinline__ void store16(float* dst, const float* bias, float f[4][8])
{
    const int t = threadIdx.x;
    const int warp = t >> 5, lane = t & 31;
    const int ty = lane >> 3, tx = lane & 7;
#pragma unroll
    for (int i = 0; i < 4; i++) {
        int ch = 16 * warp + ty * 4 + i;
        float bi = bias[ch];
#pragma unroll
        for (int j = 0; j < 8; j++) f[i][j] = lrelu(f[i][j] + bi);
        *(float4*)(dst + ch * S72 + tx * 4) =
            make_float4(f[i][0], f[i][1], f[i][2], f[i][3]);
        *(float4*)(dst + ch * S72 + 32 + tx * 4) =
            make_float4(f[i][4], f[i][5], f[i][6], f[i][7]);
    }
}

// ---------------- R1 via NS1 tf32 mma, 1 m-tile per warp (8 warps) ----------------
__device__ __forceinline__ void gemm_r1(const float* __restrict__ sIn,
                                        float acc[8][4], int w, int lane)
{
    const uint4* A0 = (const uint4*)g_wA1;
    const int g = lane >> 2, tig = lane & 3;
#pragma unroll
    for (int n = 0; n < 8; n++)
#pragma unroll
        for (int c = 0; c < 4; c++) acc[n][c] = 0.0f;

    uint4 Ab[2];
    Ab[0] = __ldg(A0 + w * 32 + lane);
#pragma unroll 1
    for (int kc = 0; kc < 16; kc++) {
        int cur = kc & 1;
        if (kc < 15)
            Ab[cur ^ 1] = __ldg(A0 + ((kc + 1) * 8 + w) * 32 + lane);
        const float* bp = sIn + (kc * 8 + tig) * S72 + g;
#pragma unroll
        for (int n = 0; n < 8; n++) {
            float x0 = bp[8 * n], x1 = bp[4 * S72 + 8 * n];
            uint32_t h0 = tf32_of(x0), h1 = tf32_of(x1);
            mma8(acc[n], Ab[cur], h0, h1);
        }
    }
}

// ---------------- fused main kernel (256 threads, 2 CTAs/SM, 16 warps/SM) ----------------
__global__ void __launch_bounds__(256, 2)
fused_kernel(const float* __restrict__ x_in,
             const float* __restrict__ cm2_b,
             const float* __restrict__ cm3_w, const float* __restrict__ cm3_b,
             float* __restrict__ out)
{
    extern __shared__ float sm[];
    float* sA   = sm;                      // x tile [128][S72] (9216 floats)
    float* sXR  = sm;                      // xr [64][TPAD] (8448, aliases sA)
    int*   sInd = (int*)(sm + 8448);       // 64 (sA tail, free after R1)
    float* sB   = sm + 9216;               // y tile [128][S72] (9216)
    float* sW   = sB + 9216;               // 8 x 128 staging (1024)
    float* sRv  = sW;                      // alias after L3: 8*64 vals
    int*   sRi  = (int*)(sW + 512);        // 8*64 idx

    const int t = threadIdx.x, w = t >> 5, lane = t & 31;
    const int ty = lane >> 3, tx = lane & 7;
    const int g = lane >> 2, tig = lane & 3;
    const int bb = blockIdx.x >> 7;
    const int w0 = (blockIdx.x & 127) * 64;
    const float* xb = x_in + (size_t)bb * 128 * 8192 + w0;

    // stage x tile [ch][S72]
#pragma unroll
    for (int j = 0; j < 8; j++) {
        int idx = t + j * 256;
        int c = idx >> 4, p4 = idx & 15;
        float4 v = *(const float4*)(xb + c * 8192 + p4 * 4);
        *(float4*)(sA + c * S72 + p4 * 4) = v;
    }
    __syncthreads();   // (1) x visible

    float f[4][8];

    // ---- L1 scalar (exact): y1 = lrelu(bn(cl1 @ x)) : sA -> sB ----
    gemm16(g_w1t, sA, sW, f);
    store16(sB, g_b1, f);

    // ---- R1 mma NS1: xr = lrelu(bn(reg1 @ x)) : sA -> sXR (transposed) ----
    {
        float acc[8][4];
        gemm_r1(sA, acc, w, lane);
        __syncthreads();   // (2) all sA reads done (L1+R1); y1 stores visible
#pragma unroll
        for (int h = 0; h < 2; h++) {
            int ch = 16 * w + 8 * h + g;
            float bi = g_br[ch];
#pragma unroll
            for (int n = 0; n < 8; n++) {
                int pos = 8 * n + 2 * tig;
                sXR[pos * TPAD + ch]       = lrelu(acc[n][2 * h]     + bi);
                sXR[(pos + 1) * TPAD + ch] = lrelu(acc[n][2 * h + 1] + bi);
            }
        }
    }

    // ---- L2 scalar (exact): y2 = lrelu(cl2 @ y1) : sB -> sB ----
    gemm16(g_w2t, sB, sW, f);
    __syncthreads();   // (3) all reads of y1 done
    store16(sB, g_b2, f);
    __syncthreads();   // (4) y2 visible

    // ---- L3 scalar (exact): logits : sB -> regs ----
    gemm16(g_w3t, sB, sW, f);
    __syncthreads();   // (5) sW staging free -> argmax alias OK

    // per-thread argmax over 4 ch, shfl-reduce over ty-groups, then cross-warp
    {
        float bv[8];
        int   bi[8];
#pragma unroll
        for (int j = 0; j < 8; j++) {
            int chb = 16 * w + ty * 4;
            float best = f[0][j] + g_b3[chb];
            int bidx = chb;
#pragma unroll
            for (int i = 1; i < 4; i++) {
                float v = f[i][j] + g_b3[chb + i];
                if (v > best) { best = v; bidx = chb + i; }
            }
            bv[j] = best; bi[j] = bidx;
        }
#pragma unroll
        for (int off = 8; off <= 16; off <<= 1)
#pragma unroll
            for (int j = 0; j < 8; j++) {
                float ov = __shfl_xor_sync(0xffffffffu, bv[j], off);
                int   oi = __shfl_xor_sync(0xffffffffu, bi[j], off);
                if (ov > bv[j] || (ov == bv[j] && oi < bi[j])) { bv[j] = ov; bi[j] = oi; }
            }
        if (lane < 8) {
#pragma unroll
            for (int j = 0; j < 8; j++) {
                int pos = (j < 4) ? (tx * 4 + j) : (32 + tx * 4 + j - 4);
                sRv[w * 64 + pos] = bv[j];
                sRi[w * 64 + pos] = bi[j];
            }
        }
    }
    __syncthreads();   // (6) argmax partials visible

    if (t < 64) {
        // reduce across 8 warps (ascending ch base -> first occurrence on ties)
        float bvv = sRv[t];
        int bii = sRi[t];
#pragma unroll
        for (int r = 1; r < 8; r++) {
            float v = sRv[r * 64 + t];
            if (v > bvv) { bvv = v; bii = sRi[r * 64 + t]; }
        }
        sInd[t] = bii;
    } else if (t < 128) {
        // mask channel: dot(y2[:,p], wm) + bm, 4 partial chains
        int p = t - 64;
        float m0 = g_bm, m1 = 0.0f, m2 = 0.0f, m3 = 0.0f;
#pragma unroll 8
        for (int k = 0; k < 128; k += 4) {
            m0 = fmaf(sB[(k + 0) * S72 + p], g_wm[k + 0], m0);
            m1 = fmaf(sB[(k + 1) * S72 + p], g_wm[k + 1], m1);
            m2 = fmaf(sB[(k + 2) * S72 + p], g_wm[k + 2], m2);
            m3 = fmaf(sB[(k + 3) * S72 + p], g_wm[k + 3], m3);
        }
        out[NPOS + bb * 8192 + w0 + p] = lrelu((m0 + m1) + (m2 + m3));
    }
    __syncthreads();   // (7) sInd visible

    // ---- MoE regression: 8 warps x 8 positions ----
#pragma unroll 1
    for (int pi = 0; pi < 8; pi++) {
        int pos = w * 8 + pi;
        int ind = sInd[pos];
        const float4* W4 = g_moe4 + ind * 1024 + lane;
        const float4* X4 = (const float4*)(sXR + pos * TPAD);
        float h[4] = {0.0f, 0.0f, 0.0f, 0.0f};
#pragma unroll
        for (int blk = 0; blk < 4; blk++) {
            float4 wv[8];
#pragma unroll
            for (int u = 0; u < 8; u++)
                wv[u] = __ldg(W4 + (blk * 8 + u) * 32);
            float4 x[8];
#pragma unroll
            for (int u = 0; u < 8; u++)
                x[u] = X4[blk * 8 + u];
#pragma unroll
            for (int u = 0; u < 8; u++) {
                float s = h[u & 3];
                s = fmaf(x[u].x, wv[u].x, s);
                s = fmaf(x[u].y, wv[u].y, s);
                s = fmaf(x[u].z, wv[u].z, s);
                s = fmaf(x[u].w, wv[u].w, s);
                h[u & 3] = s;
            }
        }
        float hs = lrelu((h[0] + h[1]) + (h[2] + h[3]) + __ldg(cm2_b + ind * 32 + lane));
        float r = hs * __ldg(cm3_w + ind * 32 + lane);
#pragma unroll
        for (int off = 16; off; off >>= 1)
            r += __shfl_down_sync(0xffffffffu, r, off);
        if (lane == 0)
            out[bb * 8192 + w0 + pos] =
                ((float)ind + r + __ldg(cm3_b + ind)) * (1.0f / 128.0f);
    }
}

// ---------------- launch ----------------
extern "C" void kernel_launch(void* const* d_in, const int* in_sizes, int n_in,
                              void* d_out, int out_size)
{
    const float* x_in  = (const float*)d_in[0];
    const float* cl1_w = (const float*)d_in[1];
    const float* cl1_b = (const float*)d_in[2];
    const float* bn1_g = (const float*)d_in[3];
    const float* bn1_b = (const float*)d_in[4];
    const float* bn1_m = (const float*)d_in[5];
    const float* bn1_v = (const float*)d_in[6];
    const float* cl2_w = (const float*)d_in[7];
    const float* cl2_b = (const float*)d_in[8];
    const float* cl3_w = (const float*)d_in[9];
    const float* cl3_b = (const float*)d_in[10];
    const float* reg1_w = (const float*)d_in[11];
    const float* reg1_b = (const float*)d_in[12];
    const float* bnr_g = (const float*)d_in[13];
    const float* bnr_b = (const float*)d_in[14];
    const float* bnr_m = (const float*)d_in[15];
    const float* bnr_v = (const float*)d_in[16];
    const float* cm2_w = (const float*)d_in[17];
    const float* cm2_b = (const float*)d_in[18];
    const float* cm3_w = (const float*)d_in[19];
    const float* cm3_b = (const float*)d_in[20];
    float* out = (float*)d_out;

    const int SMEM_BYTES = (9216 + 9216 + 1024) * 4;   // 77824 B -> 2 CTAs/SM

    cudaFuncSetAttribute(fused_kernel, cudaFuncAttributeMaxDynamicSharedMemorySize,
                         SMEM_BYTES);

    prep_kernel<<<512, 256>>>(cl1_w, cl1_b, bn1_g, bn1_b, bn1_m, bn1_v,
                              cl2_w, cl2_b, cl3_w, cl3_b,
                              reg1_w, reg1_b, bnr_g, bnr_b, bnr_m, bnr_v,
                              cm2_w);

    fused_kernel<<<1024, 256, SMEM_BYTES>>>(x_in, cm2_b, cm3_w, cm3_b, out);
}